// round 1
// baseline (speedup 1.0000x reference)
#include <cuda_runtime.h>
#include <math.h>
#include <stdint.h>

// Problem constants
#define NIMG 32
#define HWDIM 64
#define LTOK (HWDIM * HWDIM)        // 4096
#define MTOK (NIMG * LTOK)          // 131072 tokens
#define CDIM 256
#define REGC 68                      // 4*(16+1)
#define NSIDE 4
#define NBIN 17

// Output layout (flat concat): cls | boxes | reg_pred
#define OUT_CLS_OFF 0
#define OUT_BOX_OFF (MTOK)                   // 131072
#define OUT_REG_OFF (MTOK + MTOK * 4)        // 655360

// Scratch (device globals: allocation-free per harness rules)
__device__ float g_bufA[(size_t)MTOK * CDIM];
__device__ float g_bufB[(size_t)MTOK * CDIM];
__device__ float g_cls_logit[MTOK];

// ---------------------------------------------------------------------------
// Generic SGEMM: C[M,N] = A[M,K] * W[N,K]^T + bias[N]
// BM=128, BN=64, BK=16, per-thread 8x4, 256 threads.
// ---------------------------------------------------------------------------
__global__ __launch_bounds__(256) void sgemm_bias_kernel(
    const float* __restrict__ A, const float* __restrict__ W,
    const float* __restrict__ bias, float* __restrict__ C,
    int M, int N, int K)
{
    const int BM = 128, BN = 64, BK = 16;
    __shared__ float As[BK][BM];
    __shared__ float Ws[BK][BN];

    const int tid = threadIdx.x;
    const int tx = tid % 16;          // n-group
    const int ty = tid / 16;          // m-group
    const int bm = blockIdx.x * BM;
    const int bn = blockIdx.y * BN;

    float acc[8][4];
#pragma unroll
    for (int i = 0; i < 8; i++)
#pragma unroll
        for (int j = 0; j < 4; j++) acc[i][j] = 0.f;

    // global load mapping
    const int a_row = tid / 4;   // 0..63 (plus +64)
    const int a_c4  = tid % 4;   // which float4 in BK
    const int w_row = tid / 4;   // 0..63
    const int w_c4  = tid % 4;

    for (int k0 = 0; k0 < K; k0 += BK) {
#pragma unroll
        for (int r = 0; r < 2; r++) {
            int row = a_row + r * 64;
            float4 v = *reinterpret_cast<const float4*>(
                &A[(size_t)(bm + row) * K + k0 + a_c4 * 4]);
            As[a_c4 * 4 + 0][row] = v.x;
            As[a_c4 * 4 + 1][row] = v.y;
            As[a_c4 * 4 + 2][row] = v.z;
            As[a_c4 * 4 + 3][row] = v.w;
        }
        {
            float4 v = make_float4(0.f, 0.f, 0.f, 0.f);
            if (bn + w_row < N)
                v = *reinterpret_cast<const float4*>(
                    &W[(size_t)(bn + w_row) * K + k0 + w_c4 * 4]);
            Ws[w_c4 * 4 + 0][w_row] = v.x;
            Ws[w_c4 * 4 + 1][w_row] = v.y;
            Ws[w_c4 * 4 + 2][w_row] = v.z;
            Ws[w_c4 * 4 + 3][w_row] = v.w;
        }
        __syncthreads();

#pragma unroll
        for (int k = 0; k < BK; k++) {
            float a[8], b[4];
#pragma unroll
            for (int i = 0; i < 8; i++) a[i] = As[k][ty * 8 + i];
#pragma unroll
            for (int j = 0; j < 4; j++) b[j] = Ws[k][tx * 4 + j];
#pragma unroll
            for (int i = 0; i < 8; i++)
#pragma unroll
                for (int j = 0; j < 4; j++) acc[i][j] = fmaf(a[i], b[j], acc[i][j]);
        }
        __syncthreads();
    }

#pragma unroll
    for (int j = 0; j < 4; j++) {
        int n = bn + tx * 4 + j;
        if (n < N) {
            float bb = bias[n];
#pragma unroll
            for (int i = 0; i < 8; i++) {
                int m = bm + ty * 8 + i;
                C[(size_t)m * N + n] = acc[i][j] + bb;
            }
        }
    }
}

// ---------------------------------------------------------------------------
// Depthwise 3x3 conv (pad=1) + bias + exact GELU.
// Layout: in/out are [token, channel] with channel contiguous (token = n*4096 + h*64 + w)
// ---------------------------------------------------------------------------
__device__ __forceinline__ float gelu_exact(float x) {
    return 0.5f * x * (1.f + erff(x * 0.70710678118654752440f));
}

__global__ __launch_bounds__(256) void dwconv_gelu_kernel(
    const float* __restrict__ in, const float* __restrict__ w,
    const float* __restrict__ b, float* __restrict__ out)
{
    size_t idx = (size_t)blockIdx.x * 256 + threadIdx.x;   // over MTOK*CDIM
    int c = (int)(idx & (CDIM - 1));
    int l = (int)((idx >> 8) & (LTOK - 1));
    int n = (int)(idx >> 20);
    int h = l >> 6;
    int x = l & 63;

    float acc = b[c];
    const float* wc = w + c * 9;
    const float* base = in + ((size_t)n * LTOK) * CDIM;
#pragma unroll
    for (int dy = -1; dy <= 1; dy++) {
        int hh = h + dy;
        if (hh < 0 || hh >= HWDIM) continue;
#pragma unroll
        for (int dx = -1; dx <= 1; dx++) {
            int ww = x + dx;
            if (ww < 0 || ww >= HWDIM) continue;
            acc = fmaf(base[((size_t)(hh * HWDIM + ww)) * CDIM + c],
                       wc[(dy + 1) * 3 + (dx + 1)], acc);
        }
    }
    out[idx] = gelu_exact(acc);
}

// ---------------------------------------------------------------------------
// fc3 for cls branch (N=1): warp-per-token dot product, K=256.
// ---------------------------------------------------------------------------
__global__ __launch_bounds__(256) void fc_dot_kernel(
    const float* __restrict__ A, const float* __restrict__ w,
    const float* __restrict__ b, float* __restrict__ out)
{
    __shared__ float ws[CDIM];
    int tid = threadIdx.x;
    ws[tid] = w[tid];
    __syncthreads();
    int warp = tid >> 5, lane = tid & 31;
    int token = blockIdx.x * 8 + warp;
    const float* a = A + (size_t)token * CDIM;
    float acc = 0.f;
#pragma unroll
    for (int i = 0; i < 8; i++)
        acc = fmaf(a[lane + 32 * i], ws[lane + 32 * i], acc);
#pragma unroll
    for (int o = 16; o; o >>= 1) acc += __shfl_xor_sync(0xffffffffu, acc, o);
    if (lane == 0) out[token] = acc + b[0];
}

// ---------------------------------------------------------------------------
// Fused tail: softmax(17) per side -> boxes, top-4 + mean -> stat(20),
// rc1 (20->64, relu), rc2 (64->1, sigmoid) -> q ; cls = sigmoid(cls_logit)*q
// ---------------------------------------------------------------------------
__global__ __launch_bounds__(256) void fuse_tail_kernel(
    const float* __restrict__ reg, const float* __restrict__ clsl,
    const float* __restrict__ rc1w, const float* __restrict__ rc1b,
    const float* __restrict__ rc2w, const float* __restrict__ rc2b,
    float* __restrict__ cls_out, float* __restrict__ boxes_out)
{
    __shared__ float s_w1[64 * 20];
    __shared__ float s_b1[64];
    __shared__ float s_w2[64];
    int tid = threadIdx.x;
    for (int i = tid; i < 64 * 20; i += 256) s_w1[i] = rc1w[i];
    if (tid < 64) { s_b1[tid] = rc1b[tid]; s_w2[tid] = rc2w[tid]; }
    __syncthreads();

    int token = blockIdx.x * 256 + tid;
    const float* r = reg + (size_t)token * REGC;

    float stat[20];
#pragma unroll
    for (int side = 0; side < NSIDE; side++) {
        float v[NBIN];
#pragma unroll
        for (int i = 0; i < NBIN; i++) v[i] = r[side * NBIN + i];
        float m = v[0];
#pragma unroll
        for (int i = 1; i < NBIN; i++) m = fmaxf(m, v[i]);
        float p[NBIN];
        float s = 0.f, d = 0.f;
#pragma unroll
        for (int i = 0; i < NBIN; i++) {
            float e = expf(v[i] - m);
            p[i] = e;
            s += e;
            d += e * (float)i;
        }
        boxes_out[(size_t)token * 4 + side] = d / (s * 16.f);
        float inv = 1.f / s;
#pragma unroll
        for (int i = 0; i < NBIN; i++) p[i] *= inv;

        unsigned used = 0;
        float mean = 0.f;
#pragma unroll
        for (int k = 0; k < 4; k++) {
            float best = -1.f;
            int bi = 0;
#pragma unroll
            for (int i = 0; i < NBIN; i++) {
                bool ok = (((used >> i) & 1u) == 0u) && (p[i] > best);
                best = ok ? p[i] : best;
                bi = ok ? i : bi;
            }
            used |= (1u << bi);
            stat[side * 5 + k] = best;
            mean += best;
        }
        stat[side * 5 + 4] = mean * 0.25f;
    }

    float qsum = 0.f;
#pragma unroll 4
    for (int o = 0; o < 64; o++) {
        float a = s_b1[o];
#pragma unroll
        for (int c = 0; c < 20; c++) a = fmaf(s_w1[o * 20 + c], stat[c], a);
        a = fmaxf(a, 0.f);
        qsum = fmaf(s_w2[o], a, qsum);
    }
    float q = 1.f / (1.f + expf(-(qsum + rc2b[0])));
    float cl = 1.f / (1.f + expf(-clsl[token]));
    cls_out[token] = cl * q;
}

// ---------------------------------------------------------------------------
// Launch
// ---------------------------------------------------------------------------
static void run_mlp_branch(const float* x,
                           const float* fc1w, const float* fc1b,
                           const float* dw1w, const float* dw1b,
                           const float* fc2w, const float* fc2b,
                           const float* dw2w, const float* dw2b,
                           float* bufA, float* bufB)
{
    dim3 g256(MTOK / 128, CDIM / 64);
    sgemm_bias_kernel<<<g256, 256>>>(x, fc1w, fc1b, bufA, MTOK, CDIM, CDIM);
    dwconv_gelu_kernel<<<(MTOK * CDIM) / 256, 256>>>(bufA, dw1w, dw1b, bufB);
    sgemm_bias_kernel<<<g256, 256>>>(bufB, fc2w, fc2b, bufA, MTOK, CDIM, CDIM);
    dwconv_gelu_kernel<<<(MTOK * CDIM) / 256, 256>>>(bufA, dw2w, dw2b, bufB);
    // bufB now holds the post-GELU activation feeding fc3
}

extern "C" void kernel_launch(void* const* d_in, const int* in_sizes, int n_in,
                              void* d_out, int out_size)
{
    (void)in_sizes; (void)n_in; (void)out_size;
    const float* x      = (const float*)d_in[0];
    const float* c_fc1w = (const float*)d_in[1];
    const float* c_fc1b = (const float*)d_in[2];
    const float* c_dw1w = (const float*)d_in[3];
    const float* c_dw1b = (const float*)d_in[4];
    const float* c_fc2w = (const float*)d_in[5];
    const float* c_fc2b = (const float*)d_in[6];
    const float* c_dw2w = (const float*)d_in[7];
    const float* c_dw2b = (const float*)d_in[8];
    const float* c_fc3w = (const float*)d_in[9];
    const float* c_fc3b = (const float*)d_in[10];
    const float* r_fc1w = (const float*)d_in[11];
    const float* r_fc1b = (const float*)d_in[12];
    const float* r_dw1w = (const float*)d_in[13];
    const float* r_dw1b = (const float*)d_in[14];
    const float* r_fc2w = (const float*)d_in[15];
    const float* r_fc2b = (const float*)d_in[16];
    const float* r_dw2w = (const float*)d_in[17];
    const float* r_dw2b = (const float*)d_in[18];
    const float* r_fc3w = (const float*)d_in[19];
    const float* r_fc3b = (const float*)d_in[20];
    const float* rc1w   = (const float*)d_in[21];
    const float* rc1b   = (const float*)d_in[22];
    const float* rc2w   = (const float*)d_in[23];
    const float* rc2b   = (const float*)d_in[24];

    float* out = (float*)d_out;
    float* out_cls = out + OUT_CLS_OFF;
    float* out_box = out + OUT_BOX_OFF;
    float* out_reg = out + OUT_REG_OFF;

    float *bufA = nullptr, *bufB = nullptr, *clsl = nullptr;
    cudaGetSymbolAddress((void**)&bufA, g_bufA);
    cudaGetSymbolAddress((void**)&bufB, g_bufB);
    cudaGetSymbolAddress((void**)&clsl, g_cls_logit);

    // cls branch
    run_mlp_branch(x, c_fc1w, c_fc1b, c_dw1w, c_dw1b,
                   c_fc2w, c_fc2b, c_dw2w, c_dw2b, bufA, bufB);
    fc_dot_kernel<<<MTOK / 8, 256>>>(bufB, c_fc3w, c_fc3b, clsl);

    // reg branch
    run_mlp_branch(x, r_fc1w, r_fc1b, r_dw1w, r_dw1b,
                   r_fc2w, r_fc2b, r_dw2w, r_dw2b, bufA, bufB);
    {
        dim3 g68(MTOK / 128, (REGC + 63) / 64);
        sgemm_bias_kernel<<<g68, 256>>>(bufB, r_fc3w, r_fc3b, out_reg, MTOK, REGC, CDIM);
    }

    // fused tail: boxes + q + final cls
    fuse_tail_kernel<<<MTOK / 256, 256>>>(out_reg, clsl, rc1w, rc1b, rc2w, rc2b,
                                          out_cls, out_box);
}

// round 2
// speedup vs baseline: 2.1006x; 2.1006x over previous
#include <cuda_runtime.h>
#include <cuda_bf16.h>
#include <math.h>
#include <stdint.h>

// Problem constants
#define NIMG 32
#define HWDIM 64
#define LTOK (HWDIM * HWDIM)        // 4096
#define MTOK (NIMG * LTOK)          // 131072 tokens
#define CDIM 256
#define REGC 68                      // 4*(16+1)
#define NSIDE 4
#define NBIN 17

// Output layout (flat concat): cls | boxes | reg_pred
#define OUT_CLS_OFF 0
#define OUT_BOX_OFF (MTOK)
#define OUT_REG_OFF (MTOK + MTOK * 4)

// GEMM tiling
#define BM 128
#define BN 128
#define BKQ 32
#define SKA 40                       // padded smem stride (halves)
#define TILE_HALVES (128 * SKA)      // 5120
#define STAGE_BYTES (4 * TILE_HALVES * 2)   // Ahi,Alo,Whi,Wlo = 40960 B
#define GEMM_SMEM (2 * STAGE_BYTES)         // 81920 B

// Scratch (device globals: allocation-free per harness rules)
__device__ float g_bufA[(size_t)MTOK * CDIM];          // fp32 GEMM outputs
__device__ __nv_bfloat16 g_xhi[(size_t)MTOK * CDIM];   // split input x
__device__ __nv_bfloat16 g_xlo[(size_t)MTOK * CDIM];
__device__ __nv_bfloat16 g_ahi[(size_t)MTOK * CDIM];   // split activations
__device__ __nv_bfloat16 g_alo[(size_t)MTOK * CDIM];
__device__ __nv_bfloat16 g_whi[CDIM * CDIM];
__device__ __nv_bfloat16 g_wlo[CDIM * CDIM];
__device__ float g_cls_logit[MTOK];

// ---------------------------------------------------------------------------
// PTX helpers
// ---------------------------------------------------------------------------
__device__ __forceinline__ void cp16(uint32_t dst, const void* src, bool pred) {
    int bytes = pred ? 16 : 0;
    asm volatile("cp.async.cg.shared.global [%0], [%1], 16, %2;\n"
                 :: "r"(dst), "l"(src), "r"(bytes));
}
__device__ __forceinline__ void ldsm_x4(uint32_t* r, uint32_t addr) {
    asm volatile("ldmatrix.sync.aligned.m8n8.x4.shared.b16 {%0,%1,%2,%3}, [%4];"
                 : "=r"(r[0]), "=r"(r[1]), "=r"(r[2]), "=r"(r[3]) : "r"(addr));
}
__device__ __forceinline__ void ldsm_x2(uint32_t* r, uint32_t addr) {
    asm volatile("ldmatrix.sync.aligned.m8n8.x2.shared.b16 {%0,%1}, [%2];"
                 : "=r"(r[0]), "=r"(r[1]) : "r"(addr));
}
__device__ __forceinline__ void mma16816(float* c, const uint32_t* a, const uint32_t* b) {
    asm volatile("mma.sync.aligned.m16n8k16.row.col.f32.bf16.bf16.f32 "
                 "{%0,%1,%2,%3}, {%4,%5,%6,%7}, {%8,%9}, {%0,%1,%2,%3};"
                 : "+f"(c[0]), "+f"(c[1]), "+f"(c[2]), "+f"(c[3])
                 : "r"(a[0]), "r"(a[1]), "r"(a[2]), "r"(a[3]), "r"(b[0]), "r"(b[1]));
}

__device__ __forceinline__ float gelu_exact(float x) {
    return 0.5f * x * (1.f + erff(x * 0.70710678118654752440f));
}

// ---------------------------------------------------------------------------
// Split conversions (fp32 -> bf16 hi + bf16 lo)
// ---------------------------------------------------------------------------
__global__ __launch_bounds__(256) void convert_x_kernel(
    const float* __restrict__ x, __nv_bfloat16* __restrict__ hi,
    __nv_bfloat16* __restrict__ lo)
{
    size_t base = ((size_t)blockIdx.x * 256 + threadIdx.x) * 4;
    float4 v = *reinterpret_cast<const float4*>(x + base);
    __nv_bfloat16 h0 = __float2bfloat16(v.x);
    __nv_bfloat16 h1 = __float2bfloat16(v.y);
    __nv_bfloat16 h2 = __float2bfloat16(v.z);
    __nv_bfloat16 h3 = __float2bfloat16(v.w);
    __nv_bfloat162* hp = reinterpret_cast<__nv_bfloat162*>(hi + base);
    hp[0] = __nv_bfloat162(h0, h1);
    hp[1] = __nv_bfloat162(h2, h3);
    __nv_bfloat162* lp = reinterpret_cast<__nv_bfloat162*>(lo + base);
    lp[0] = __nv_bfloat162(__float2bfloat16(v.x - __bfloat162float(h0)),
                           __float2bfloat16(v.y - __bfloat162float(h1)));
    lp[1] = __nv_bfloat162(__float2bfloat16(v.z - __bfloat162float(h2)),
                           __float2bfloat16(v.w - __bfloat162float(h3)));
}

__global__ __launch_bounds__(256) void convert_w_kernel(
    const float* __restrict__ w, __nv_bfloat16* __restrict__ hi,
    __nv_bfloat16* __restrict__ lo, int n)
{
    int i = blockIdx.x * 256 + threadIdx.x;
    if (i < n) {
        float v = w[i];
        __nv_bfloat16 h = __float2bfloat16(v);
        hi[i] = h;
        lo[i] = __float2bfloat16(v - __bfloat162float(h));
    }
}

// ---------------------------------------------------------------------------
// Tensor-core GEMM: C[M,N] = (Ahi+Alo)[M,K] @ (Whi+Wlo)[N,K]^T + bias
// bf16x3: hh + lh + hl terms, fp32 accumulate. K = 256 fixed.
// ---------------------------------------------------------------------------
__global__ __launch_bounds__(256) void gemm_bf16x3_kernel(
    const __nv_bfloat16* __restrict__ Ahi, const __nv_bfloat16* __restrict__ Alo,
    const __nv_bfloat16* __restrict__ Whi, const __nv_bfloat16* __restrict__ Wlo,
    const float* __restrict__ bias, float* __restrict__ C, int Ntot)
{
    extern __shared__ __align__(16) __nv_bfloat16 sm[];
    const int tid = threadIdx.x;
    const int lane = tid & 31, warp = tid >> 5;
    const int wm = warp >> 2, wn = warp & 3;   // 2 x 4 warp grid
    const int bm = blockIdx.x * BM, bn = blockIdx.y * BN;
    uint32_t sb = (uint32_t)__cvta_generic_to_shared(sm);

    const uint32_t AHI = 0;
    const uint32_t ALO = TILE_HALVES * 2;
    const uint32_t WHI = 2 * TILE_HALVES * 2;
    const uint32_t WLO = 3 * TILE_HALVES * 2;

    float acc[4][4][4];
#pragma unroll
    for (int a = 0; a < 4; a++)
#pragma unroll
        for (int b = 0; b < 4; b++)
#pragma unroll
            for (int c = 0; c < 4; c++) acc[a][b][c] = 0.f;

    auto load_stage = [&](int s, int k0) {
        uint32_t st = sb + s * STAGE_BYTES;
#pragma unroll
        for (int t = 0; t < 2; t++) {
            int chunk = tid + t * 256;
            int row = chunk >> 2;
            int c16 = (chunk & 3) * 8;
            uint32_t sOff = (uint32_t)(row * SKA + c16) * 2;
            size_t ga = (size_t)(bm + row) * CDIM + k0 + c16;
            cp16(st + AHI + sOff, Ahi + ga, true);
            cp16(st + ALO + sOff, Alo + ga, true);
            bool wp = (bn + row) < Ntot;
            size_t gw = (size_t)(bn + row) * CDIM + k0 + c16;
            cp16(st + WHI + sOff, Whi + gw, wp);
            cp16(st + WLO + sOff, Wlo + gw, wp);
        }
    };

    load_stage(0, 0);
    asm volatile("cp.async.commit_group;");

    const int arow = lane & 15, acol = (lane >> 4) * 8;
    const int brow = lane & 7, bcol = ((lane >> 3) & 1) * 8;

    for (int it = 0; it < 8; it++) {
        if (it + 1 < 8) load_stage((it + 1) & 1, (it + 1) * BKQ);
        asm volatile("cp.async.commit_group;");
        asm volatile("cp.async.wait_group 1;");
        __syncthreads();
        uint32_t st = sb + (it & 1) * STAGE_BYTES;
#pragma unroll
        for (int ks = 0; ks < 2; ks++) {
            int kb = ks * 16;
            uint32_t ah[4][4], al[4][4], bf[4][2];
#pragma unroll
            for (int mf = 0; mf < 4; mf++) {
                uint32_t ao = (uint32_t)((wm * 64 + mf * 16 + arow) * SKA + kb + acol) * 2;
                ldsm_x4(ah[mf], st + AHI + ao);
                ldsm_x4(al[mf], st + ALO + ao);
            }
#pragma unroll
            for (int nf = 0; nf < 4; nf++) {
                uint32_t bo = (uint32_t)((wn * 32 + nf * 8 + brow) * SKA + kb + bcol) * 2;
                ldsm_x2(bf[nf], st + WHI + bo);
            }
#pragma unroll
            for (int mf = 0; mf < 4; mf++)
#pragma unroll
                for (int nf = 0; nf < 4; nf++) {
                    mma16816(acc[mf][nf], ah[mf], bf[nf]);   // hi*hi
                    mma16816(acc[mf][nf], al[mf], bf[nf]);   // lo*hi
                }
#pragma unroll
            for (int nf = 0; nf < 4; nf++) {
                uint32_t bo = (uint32_t)((wn * 32 + nf * 8 + brow) * SKA + kb + bcol) * 2;
                ldsm_x2(bf[nf], st + WLO + bo);
            }
#pragma unroll
            for (int mf = 0; mf < 4; mf++)
#pragma unroll
                for (int nf = 0; nf < 4; nf++)
                    mma16816(acc[mf][nf], ah[mf], bf[nf]);   // hi*lo
        }
        __syncthreads();
    }

    // Epilogue: bias + store fp32
#pragma unroll
    for (int mf = 0; mf < 4; mf++) {
        int r0 = bm + wm * 64 + mf * 16 + (lane >> 2);
#pragma unroll
        for (int nf = 0; nf < 4; nf++) {
            int c = bn + wn * 32 + nf * 8 + (lane & 3) * 2;
            if (c < Ntot) {   // Ntot even, c even => c+1 also valid
                float b0 = bias[c], b1 = bias[c + 1];
                float2 v0 = make_float2(acc[mf][nf][0] + b0, acc[mf][nf][1] + b1);
                float2 v1 = make_float2(acc[mf][nf][2] + b0, acc[mf][nf][3] + b1);
                *reinterpret_cast<float2*>(C + (size_t)r0 * Ntot + c) = v0;
                *reinterpret_cast<float2*>(C + (size_t)(r0 + 8) * Ntot + c) = v1;
            }
        }
    }
}

// ---------------------------------------------------------------------------
// Depthwise 3x3 + bias + exact GELU, fp32 in -> bf16 hi/lo out.
// Thread: 4 channels (float4) x 4 tokens; weights in registers.
// ---------------------------------------------------------------------------
__global__ __launch_bounds__(256) void dwconv_gelu_split_kernel(
    const float* __restrict__ in, const float* __restrict__ w,
    const float* __restrict__ b,
    __nv_bfloat16* __restrict__ ohi, __nv_bfloat16* __restrict__ olo)
{
    int tid = threadIdx.x;
    int g = tid & 63;        // channel group: channels 4g..4g+3
    int ty = tid >> 6;       // 0..3
    int c0 = g * 4;

    float wr[3][3][4];
#pragma unroll
    for (int k = 0; k < 9; k++)
#pragma unroll
        for (int j = 0; j < 4; j++)
            wr[k / 3][k % 3][j] = w[(c0 + j) * 9 + k];
    float4 bb = *reinterpret_cast<const float4*>(b + c0);

    int tbase = blockIdx.x * 16;
#pragma unroll
    for (int i = 0; i < 4; i++) {
        int token = tbase + i * 4 + ty;
        int n = token >> 12;
        int l = token & 4095;
        int h = l >> 6, xx = l & 63;
        float4 acc = bb;
        const float* base = in + (size_t)(n << 12) * CDIM + c0;
#pragma unroll
        for (int dy = -1; dy <= 1; dy++) {
            int hh = h + dy;
            if ((unsigned)hh >= HWDIM) continue;
#pragma unroll
            for (int dx = -1; dx <= 1; dx++) {
                int ww = xx + dx;
                if ((unsigned)ww >= HWDIM) continue;
                float4 v = *reinterpret_cast<const float4*>(
                    base + (size_t)((hh << 6) + ww) * CDIM);
                acc.x = fmaf(v.x, wr[dy + 1][dx + 1][0], acc.x);
                acc.y = fmaf(v.y, wr[dy + 1][dx + 1][1], acc.y);
                acc.z = fmaf(v.z, wr[dy + 1][dx + 1][2], acc.z);
                acc.w = fmaf(v.w, wr[dy + 1][dx + 1][3], acc.w);
            }
        }
        float o0 = gelu_exact(acc.x), o1 = gelu_exact(acc.y);
        float o2 = gelu_exact(acc.z), o3 = gelu_exact(acc.w);
        __nv_bfloat16 h0 = __float2bfloat16(o0), h1 = __float2bfloat16(o1);
        __nv_bfloat16 h2 = __float2bfloat16(o2), h3 = __float2bfloat16(o3);
        size_t idx = (size_t)token * CDIM + c0;
        __nv_bfloat162* hp = reinterpret_cast<__nv_bfloat162*>(ohi + idx);
        hp[0] = __nv_bfloat162(h0, h1);
        hp[1] = __nv_bfloat162(h2, h3);
        __nv_bfloat162* lp = reinterpret_cast<__nv_bfloat162*>(olo + idx);
        lp[0] = __nv_bfloat162(__float2bfloat16(o0 - __bfloat162float(h0)),
                               __float2bfloat16(o1 - __bfloat162float(h1)));
        lp[1] = __nv_bfloat162(__float2bfloat16(o2 - __bfloat162float(h2)),
                               __float2bfloat16(o3 - __bfloat162float(h3)));
    }
}

// ---------------------------------------------------------------------------
// fc3 for cls branch (N=1): warp-per-token dot, K=256, reads hi/lo activation.
// ---------------------------------------------------------------------------
__global__ __launch_bounds__(256) void fc_dot_kernel(
    const __nv_bfloat16* __restrict__ Ahi, const __nv_bfloat16* __restrict__ Alo,
    const float* __restrict__ w, const float* __restrict__ b,
    float* __restrict__ out)
{
    __shared__ float ws[CDIM];
    int tid = threadIdx.x;
    ws[tid] = w[tid];
    __syncthreads();
    int warp = tid >> 5, lane = tid & 31;
    int token = blockIdx.x * 8 + warp;
    const __nv_bfloat16* ah = Ahi + (size_t)token * CDIM;
    const __nv_bfloat16* al = Alo + (size_t)token * CDIM;
    float acc = 0.f;
#pragma unroll
    for (int i = 0; i < 8; i++) {
        int k = lane + 32 * i;
        float a = __bfloat162float(ah[k]) + __bfloat162float(al[k]);
        acc = fmaf(a, ws[k], acc);
    }
#pragma unroll
    for (int o = 16; o; o >>= 1) acc += __shfl_xor_sync(0xffffffffu, acc, o);
    if (lane == 0) out[token] = acc + b[0];
}

// ---------------------------------------------------------------------------
// Fused tail: softmax(17) -> boxes, top-4+mean -> rc1(relu) -> rc2(sigmoid),
// cls = sigmoid(cls_logit) * q
// ---------------------------------------------------------------------------
__global__ __launch_bounds__(256) void fuse_tail_kernel(
    const float* __restrict__ reg, const float* __restrict__ clsl,
    const float* __restrict__ rc1w, const float* __restrict__ rc1b,
    const float* __restrict__ rc2w, const float* __restrict__ rc2b,
    float* __restrict__ cls_out, float* __restrict__ boxes_out)
{
    __shared__ float s_w1[64 * 20];
    __shared__ float s_b1[64];
    __shared__ float s_w2[64];
    int tid = threadIdx.x;
    for (int i = tid; i < 64 * 20; i += 256) s_w1[i] = rc1w[i];
    if (tid < 64) { s_b1[tid] = rc1b[tid]; s_w2[tid] = rc2w[tid]; }
    __syncthreads();

    int token = blockIdx.x * 256 + tid;
    const float* r = reg + (size_t)token * REGC;

    float stat[20];
#pragma unroll
    for (int side = 0; side < NSIDE; side++) {
        float v[NBIN];
#pragma unroll
        for (int i = 0; i < NBIN; i++) v[i] = r[side * NBIN + i];
        float m = v[0];
#pragma unroll
        for (int i = 1; i < NBIN; i++) m = fmaxf(m, v[i]);
        float p[NBIN];
        float s = 0.f, d = 0.f;
#pragma unroll
        for (int i = 0; i < NBIN; i++) {
            float e = expf(v[i] - m);
            p[i] = e;
            s += e;
            d += e * (float)i;
        }
        boxes_out[(size_t)token * 4 + side] = d / (s * 16.f);
        float inv = 1.f / s;
#pragma unroll
        for (int i = 0; i < NBIN; i++) p[i] *= inv;

        unsigned used = 0;
        float mean = 0.f;
#pragma unroll
        for (int k = 0; k < 4; k++) {
            float best = -1.f;
            int bi = 0;
#pragma unroll
            for (int i = 0; i < NBIN; i++) {
                bool ok = (((used >> i) & 1u) == 0u) && (p[i] > best);
                best = ok ? p[i] : best;
                bi = ok ? i : bi;
            }
            used |= (1u << bi);
            stat[side * 5 + k] = best;
            mean += best;
        }
        stat[side * 5 + 4] = mean * 0.25f;
    }

    float qsum = 0.f;
#pragma unroll 4
    for (int o = 0; o < 64; o++) {
        float a = s_b1[o];
#pragma unroll
        for (int c = 0; c < 20; c++) a = fmaf(s_w1[o * 20 + c], stat[c], a);
        a = fmaxf(a, 0.f);
        qsum = fmaf(s_w2[o], a, qsum);
    }
    float q = 1.f / (1.f + expf(-(qsum + rc2b[0])));
    float cl = 1.f / (1.f + expf(-clsl[token]));
    cls_out[token] = cl * q;
}

// ---------------------------------------------------------------------------
// Launch
// ---------------------------------------------------------------------------
extern "C" void kernel_launch(void* const* d_in, const int* in_sizes, int n_in,
                              void* d_out, int out_size)
{
    (void)in_sizes; (void)n_in; (void)out_size;
    const float* x      = (const float*)d_in[0];
    const float* c_fc1w = (const float*)d_in[1];
    const float* c_fc1b = (const float*)d_in[2];
    const float* c_dw1w = (const float*)d_in[3];
    const float* c_dw1b = (const float*)d_in[4];
    const float* c_fc2w = (const float*)d_in[5];
    const float* c_fc2b = (const float*)d_in[6];
    const float* c_dw2w = (const float*)d_in[7];
    const float* c_dw2b = (const float*)d_in[8];
    const float* c_fc3w = (const float*)d_in[9];
    const float* c_fc3b = (const float*)d_in[10];
    const float* r_fc1w = (const float*)d_in[11];
    const float* r_fc1b = (const float*)d_in[12];
    const float* r_dw1w = (const float*)d_in[13];
    const float* r_dw1b = (const float*)d_in[14];
    const float* r_fc2w = (const float*)d_in[15];
    const float* r_fc2b = (const float*)d_in[16];
    const float* r_dw2w = (const float*)d_in[17];
    const float* r_dw2b = (const float*)d_in[18];
    const float* r_fc3w = (const float*)d_in[19];
    const float* r_fc3b = (const float*)d_in[20];
    const float* rc1w   = (const float*)d_in[21];
    const float* rc1b   = (const float*)d_in[22];
    const float* rc2w   = (const float*)d_in[23];
    const float* rc2b   = (const float*)d_in[24];

    float* out = (float*)d_out;
    float* out_cls = out + OUT_CLS_OFF;
    float* out_box = out + OUT_BOX_OFF;
    float* out_reg = out + OUT_REG_OFF;

    float *bufA = nullptr, *clsl = nullptr;
    __nv_bfloat16 *xhi, *xlo, *ahi, *alo, *whi, *wlo;
    cudaGetSymbolAddress((void**)&bufA, g_bufA);
    cudaGetSymbolAddress((void**)&clsl, g_cls_logit);
    cudaGetSymbolAddress((void**)&xhi, g_xhi);
    cudaGetSymbolAddress((void**)&xlo, g_xlo);
    cudaGetSymbolAddress((void**)&ahi, g_ahi);
    cudaGetSymbolAddress((void**)&alo, g_alo);
    cudaGetSymbolAddress((void**)&whi, g_whi);
    cudaGetSymbolAddress((void**)&wlo, g_wlo);

    cudaFuncSetAttribute(gemm_bf16x3_kernel,
                         cudaFuncAttributeMaxDynamicSharedMemorySize, GEMM_SMEM);

    // x -> bf16 split (shared by both branches)
    convert_x_kernel<<<(MTOK * CDIM) / 1024, 256>>>(x, xhi, xlo);

    auto gemm = [&](const __nv_bfloat16* Ah, const __nv_bfloat16* Al,
                    const float* W, const float* B, float* Cout, int N) {
        convert_w_kernel<<<(N * CDIM + 255) / 256, 256>>>(W, whi, wlo, N * CDIM);
        dim3 grid(MTOK / BM, (N + BN - 1) / BN);
        gemm_bf16x3_kernel<<<grid, 256, GEMM_SMEM>>>(Ah, Al, whi, wlo, B, Cout, N);
    };

    // ---- cls branch ----
    gemm(xhi, xlo, c_fc1w, c_fc1b, bufA, CDIM);
    dwconv_gelu_split_kernel<<<MTOK / 16, 256>>>(bufA, c_dw1w, c_dw1b, ahi, alo);
    gemm(ahi, alo, c_fc2w, c_fc2b, bufA, CDIM);
    dwconv_gelu_split_kernel<<<MTOK / 16, 256>>>(bufA, c_dw2w, c_dw2b, ahi, alo);
    fc_dot_kernel<<<MTOK / 8, 256>>>(ahi, alo, c_fc3w, c_fc3b, clsl);

    // ---- reg branch ----
    gemm(xhi, xlo, r_fc1w, r_fc1b, bufA, CDIM);
    dwconv_gelu_split_kernel<<<MTOK / 16, 256>>>(bufA, r_dw1w, r_dw1b, ahi, alo);
    gemm(ahi, alo, r_fc2w, r_fc2b, bufA, CDIM);
    dwconv_gelu_split_kernel<<<MTOK / 16, 256>>>(bufA, r_dw2w, r_dw2b, ahi, alo);
    gemm(ahi, alo, r_fc3w, r_fc3b, out_reg, REGC);

    // ---- fused tail ----
    fuse_tail_kernel<<<MTOK / 256, 256>>>(out_reg, clsl, rc1w, rc1b, rc2w, rc2b,
                                          out_cls, out_box);
}

// round 3
// speedup vs baseline: 2.3523x; 1.1199x over previous
#include <cuda_runtime.h>
#include <cuda_bf16.h>
#include <math.h>
#include <stdint.h>

// Problem constants
#define NIMG 32
#define HWDIM 64
#define LTOK (HWDIM * HWDIM)        // 4096
#define MTOK (NIMG * LTOK)          // 131072 tokens
#define CDIM 256
#define REGC 68                      // 4*(16+1)
#define NSIDE 4
#define NBIN 17

// Output layout (flat concat): cls | boxes | reg_pred
#define OUT_CLS_OFF 0
#define OUT_BOX_OFF (MTOK)
#define OUT_REG_OFF (MTOK + MTOK * 4)

// GEMM tiling
#define BM 128
#define BN 128
#define BKQ 32
#define SKA 40                       // padded smem stride (halves)
#define TILE_HALVES (128 * SKA)      // 5120
#define STAGE_BYTES (4 * TILE_HALVES * 2)   // Ahi,Alo,Whi,Wlo = 40960 B
#define GEMM_SMEM (2 * STAGE_BYTES)         // 81920 B

// Weight buffer offsets (bf16 hi/lo for all GEMM weights)
#define WOFF_CFC1 0
#define WOFF_CFC2 65536
#define WOFF_RFC1 131072
#define WOFF_RFC2 196608
#define WOFF_RFC3 262144
#define WTOTAL    (262144 + REGC * CDIM)    // 279552

// Scratch (device globals: allocation-free per harness rules)
__device__ float g_bufA[(size_t)MTOK * CDIM];          // fp32 GEMM outputs
__device__ __nv_bfloat16 g_xhi[(size_t)MTOK * CDIM];   // split input x
__device__ __nv_bfloat16 g_xlo[(size_t)MTOK * CDIM];
__device__ __nv_bfloat16 g_ahi[(size_t)MTOK * CDIM];   // split activations
__device__ __nv_bfloat16 g_alo[(size_t)MTOK * CDIM];
__device__ __nv_bfloat16 g_whi[WTOTAL];
__device__ __nv_bfloat16 g_wlo[WTOTAL];
__device__ float g_cls_logit[MTOK];

// ---------------------------------------------------------------------------
// PTX helpers
// ---------------------------------------------------------------------------
__device__ __forceinline__ void cp16(uint32_t dst, const void* src, bool pred) {
    int bytes = pred ? 16 : 0;
    asm volatile("cp.async.cg.shared.global [%0], [%1], 16, %2;\n"
                 :: "r"(dst), "l"(src), "r"(bytes));
}
__device__ __forceinline__ void ldsm_x4(uint32_t* r, uint32_t addr) {
    asm volatile("ldmatrix.sync.aligned.m8n8.x4.shared.b16 {%0,%1,%2,%3}, [%4];"
                 : "=r"(r[0]), "=r"(r[1]), "=r"(r[2]), "=r"(r[3]) : "r"(addr));
}
__device__ __forceinline__ void ldsm_x2(uint32_t* r, uint32_t addr) {
    asm volatile("ldmatrix.sync.aligned.m8n8.x2.shared.b16 {%0,%1}, [%2];"
                 : "=r"(r[0]), "=r"(r[1]) : "r"(addr));
}
__device__ __forceinline__ void mma16816(float* c, const uint32_t* a, const uint32_t* b) {
    asm volatile("mma.sync.aligned.m16n8k16.row.col.f32.bf16.bf16.f32 "
                 "{%0,%1,%2,%3}, {%4,%5,%6,%7}, {%8,%9}, {%0,%1,%2,%3};"
                 : "+f"(c[0]), "+f"(c[1]), "+f"(c[2]), "+f"(c[3])
                 : "r"(a[0]), "r"(a[1]), "r"(a[2]), "r"(a[3]), "r"(b[0]), "r"(b[1]));
}

__device__ __forceinline__ float gelu_exact(float x) {
    return 0.5f * x * (1.f + erff(x * 0.70710678118654752440f));
}

// ---------------------------------------------------------------------------
// Split conversions (fp32 -> bf16 hi + bf16 lo)
// ---------------------------------------------------------------------------
__global__ __launch_bounds__(256) void convert_x_kernel(
    const float* __restrict__ x, __nv_bfloat16* __restrict__ hi,
    __nv_bfloat16* __restrict__ lo)
{
    size_t base = ((size_t)blockIdx.x * 256 + threadIdx.x) * 4;
    float4 v = *reinterpret_cast<const float4*>(x + base);
    __nv_bfloat16 h0 = __float2bfloat16(v.x);
    __nv_bfloat16 h1 = __float2bfloat16(v.y);
    __nv_bfloat16 h2 = __float2bfloat16(v.z);
    __nv_bfloat16 h3 = __float2bfloat16(v.w);
    __nv_bfloat162* hp = reinterpret_cast<__nv_bfloat162*>(hi + base);
    hp[0] = __nv_bfloat162(h0, h1);
    hp[1] = __nv_bfloat162(h2, h3);
    __nv_bfloat162* lp = reinterpret_cast<__nv_bfloat162*>(lo + base);
    lp[0] = __nv_bfloat162(__float2bfloat16(v.x - __bfloat162float(h0)),
                           __float2bfloat16(v.y - __bfloat162float(h1)));
    lp[1] = __nv_bfloat162(__float2bfloat16(v.z - __bfloat162float(h2)),
                           __float2bfloat16(v.w - __bfloat162float(h3)));
}

// Convert all five GEMM weight matrices in one launch.
__global__ __launch_bounds__(256) void convert_w5_kernel(
    const float* __restrict__ w0, const float* __restrict__ w1,
    const float* __restrict__ w2, const float* __restrict__ w3,
    const float* __restrict__ w4,
    __nv_bfloat16* __restrict__ hi, __nv_bfloat16* __restrict__ lo)
{
    int i = blockIdx.x * 256 + threadIdx.x;
    if (i >= WTOTAL) return;
    const float* src; int off;
    if      (i < WOFF_CFC2) { src = w0; off = WOFF_CFC1; }
    else if (i < WOFF_RFC1) { src = w1; off = WOFF_CFC2; }
    else if (i < WOFF_RFC2) { src = w2; off = WOFF_RFC1; }
    else if (i < WOFF_RFC3) { src = w3; off = WOFF_RFC2; }
    else                    { src = w4; off = WOFF_RFC3; }
    float v = src[i - off];
    __nv_bfloat16 h = __float2bfloat16(v);
    hi[i] = h;
    lo[i] = __float2bfloat16(v - __bfloat162float(h));
}

// ---------------------------------------------------------------------------
// Tensor-core GEMM: C[M,N] = (Ahi+Alo)[M,K] @ (Whi+Wlo)[N,K]^T + bias
// bf16x3: hh + lh + hl terms, fp32 accumulate. K = 256 fixed.
// ---------------------------------------------------------------------------
__global__ __launch_bounds__(256) void gemm_bf16x3_kernel(
    const __nv_bfloat16* __restrict__ Ahi, const __nv_bfloat16* __restrict__ Alo,
    const __nv_bfloat16* __restrict__ Whi, const __nv_bfloat16* __restrict__ Wlo,
    const float* __restrict__ bias, float* __restrict__ C, int Ntot)
{
    extern __shared__ __align__(16) __nv_bfloat16 sm[];
    const int tid = threadIdx.x;
    const int lane = tid & 31, warp = tid >> 5;
    const int wm = warp >> 2, wn = warp & 3;   // 2 x 4 warp grid
    const int bm = blockIdx.x * BM, bn = blockIdx.y * BN;
    uint32_t sb = (uint32_t)__cvta_generic_to_shared(sm);

    const uint32_t AHI = 0;
    const uint32_t ALO = TILE_HALVES * 2;
    const uint32_t WHI = 2 * TILE_HALVES * 2;
    const uint32_t WLO = 3 * TILE_HALVES * 2;

    float acc[4][4][4];
#pragma unroll
    for (int a = 0; a < 4; a++)
#pragma unroll
        for (int b = 0; b < 4; b++)
#pragma unroll
            for (int c = 0; c < 4; c++) acc[a][b][c] = 0.f;

    auto load_stage = [&](int s, int k0) {
        uint32_t st = sb + s * STAGE_BYTES;
#pragma unroll
        for (int t = 0; t < 2; t++) {
            int chunk = tid + t * 256;
            int row = chunk >> 2;
            int c16 = (chunk & 3) * 8;
            uint32_t sOff = (uint32_t)(row * SKA + c16) * 2;
            size_t ga = (size_t)(bm + row) * CDIM + k0 + c16;
            cp16(st + AHI + sOff, Ahi + ga, true);
            cp16(st + ALO + sOff, Alo + ga, true);
            bool wp = (bn + row) < Ntot;
            size_t gw = (size_t)(bn + row) * CDIM + k0 + c16;
            cp16(st + WHI + sOff, Whi + gw, wp);
            cp16(st + WLO + sOff, Wlo + gw, wp);
        }
    };

    load_stage(0, 0);
    asm volatile("cp.async.commit_group;");

    const int arow = lane & 15, acol = (lane >> 4) * 8;
    const int brow = lane & 7, bcol = ((lane >> 3) & 1) * 8;

    for (int it = 0; it < 8; it++) {
        if (it + 1 < 8) load_stage((it + 1) & 1, (it + 1) * BKQ);
        asm volatile("cp.async.commit_group;");
        asm volatile("cp.async.wait_group 1;");
        __syncthreads();
        uint32_t st = sb + (it & 1) * STAGE_BYTES;
#pragma unroll
        for (int ks = 0; ks < 2; ks++) {
            int kb = ks * 16;
            uint32_t ah[4][4], al[4][4], bf[4][2];
#pragma unroll
            for (int mf = 0; mf < 4; mf++) {
                uint32_t ao = (uint32_t)((wm * 64 + mf * 16 + arow) * SKA + kb + acol) * 2;
                ldsm_x4(ah[mf], st + AHI + ao);
                ldsm_x4(al[mf], st + ALO + ao);
            }
#pragma unroll
            for (int nf = 0; nf < 4; nf++) {
                uint32_t bo = (uint32_t)((wn * 32 + nf * 8 + brow) * SKA + kb + bcol) * 2;
                ldsm_x2(bf[nf], st + WHI + bo);
            }
#pragma unroll
            for (int mf = 0; mf < 4; mf++)
#pragma unroll
                for (int nf = 0; nf < 4; nf++) {
                    mma16816(acc[mf][nf], ah[mf], bf[nf]);   // hi*hi
                    mma16816(acc[mf][nf], al[mf], bf[nf]);   // lo*hi
                }
#pragma unroll
            for (int nf = 0; nf < 4; nf++) {
                uint32_t bo = (uint32_t)((wn * 32 + nf * 8 + brow) * SKA + kb + bcol) * 2;
                ldsm_x2(bf[nf], st + WLO + bo);
            }
#pragma unroll
            for (int mf = 0; mf < 4; mf++)
#pragma unroll
                for (int nf = 0; nf < 4; nf++)
                    mma16816(acc[mf][nf], ah[mf], bf[nf]);   // hi*lo
        }
        __syncthreads();
    }

    // Epilogue: bias + store fp32
#pragma unroll
    for (int mf = 0; mf < 4; mf++) {
        int r0 = bm + wm * 64 + mf * 16 + (lane >> 2);
#pragma unroll
        for (int nf = 0; nf < 4; nf++) {
            int c = bn + wn * 32 + nf * 8 + (lane & 3) * 2;
            if (c < Ntot) {   // Ntot even, c even => c+1 also valid
                float b0 = bias[c], b1 = bias[c + 1];
                float2 v0 = make_float2(acc[mf][nf][0] + b0, acc[mf][nf][1] + b1);
                float2 v1 = make_float2(acc[mf][nf][2] + b0, acc[mf][nf][3] + b1);
                *reinterpret_cast<float2*>(C + (size_t)r0 * Ntot + c) = v0;
                *reinterpret_cast<float2*>(C + (size_t)(r0 + 8) * Ntot + c) = v1;
            }
        }
    }
}

// ---------------------------------------------------------------------------
// Depthwise 3x3 + bias + exact GELU, fp32 in -> bf16 hi/lo out.
// Sliding-window: thread = (4-channel group, 16-column row segment).
// 3 column loads per output instead of 9.
// ---------------------------------------------------------------------------
__device__ __forceinline__ float4 ld4p(const float* p, bool pred) {
    return pred ? *reinterpret_cast<const float4*>(p) : make_float4(0.f, 0.f, 0.f, 0.f);
}

__global__ __launch_bounds__(256) void dwconv_gelu_split_kernel(
    const float* __restrict__ in, const float* __restrict__ w,
    const float* __restrict__ b,
    __nv_bfloat16* __restrict__ ohi, __nv_bfloat16* __restrict__ olo)
{
    const int tid = threadIdx.x;
    const int g = tid & 63;        // channel group: channels 4g..4g+3
    const int seg = tid >> 6;      // 0..3, 16 columns each
    const int c0 = g * 4;
    const int r = blockIdx.x;      // global row 0..2047
    const int h = r & 63;
    const int x0 = seg * 16;

    // weights for 4 channels: wr[dy][dx] = float4 across channels
    float4 wr[3][3];
#pragma unroll
    for (int dy = 0; dy < 3; dy++)
#pragma unroll
        for (int dx = 0; dx < 3; dx++) {
            int k = dy * 3 + dx;
            wr[dy][dx] = make_float4(w[(c0 + 0) * 9 + k], w[(c0 + 1) * 9 + k],
                                     w[(c0 + 2) * 9 + k], w[(c0 + 3) * 9 + k]);
        }
    const float4 bb = *reinterpret_cast<const float4*>(b + c0);

    const bool up = h > 0, dn = h < 63;
    const float* base = in + ((size_t)r * 64) * CDIM + c0;   // column 0 of this row

    float4 colA[3], colB[3], colC[3];
    // load columns x0-1 and x0
    {
        bool xv = x0 > 0;   // x0-1 valid only if x0 >= 1
        const float* p = base + (size_t)(x0 - 1) * CDIM;
        colA[0] = ld4p(p - 64 * CDIM, xv && up);
        colA[1] = ld4p(p, xv);
        colA[2] = ld4p(p + 64 * CDIM, xv && dn);
        const float* q = base + (size_t)x0 * CDIM;
        colB[0] = ld4p(q - 64 * CDIM, up);
        colB[1] = ld4p(q, true);
        colB[2] = ld4p(q + 64 * CDIM, dn);
    }

#pragma unroll
    for (int j = 0; j < 16; j++) {
        int x = x0 + j;
        {
            bool xv = (x + 1) < 64;
            const float* p = base + (size_t)(x + 1) * CDIM;
            colC[0] = ld4p(p - 64 * CDIM, xv && up);
            colC[1] = ld4p(p, xv);
            colC[2] = ld4p(p + 64 * CDIM, xv && dn);
        }
        float4 acc = bb;
#pragma unroll
        for (int dy = 0; dy < 3; dy++) {
            acc.x = fmaf(colA[dy].x, wr[dy][0].x, acc.x);
            acc.y = fmaf(colA[dy].y, wr[dy][0].y, acc.y);
            acc.z = fmaf(colA[dy].z, wr[dy][0].z, acc.z);
            acc.w = fmaf(colA[dy].w, wr[dy][0].w, acc.w);
            acc.x = fmaf(colB[dy].x, wr[dy][1].x, acc.x);
            acc.y = fmaf(colB[dy].y, wr[dy][1].y, acc.y);
            acc.z = fmaf(colB[dy].z, wr[dy][1].z, acc.z);
            acc.w = fmaf(colB[dy].w, wr[dy][1].w, acc.w);
            acc.x = fmaf(colC[dy].x, wr[dy][2].x, acc.x);
            acc.y = fmaf(colC[dy].y, wr[dy][2].y, acc.y);
            acc.z = fmaf(colC[dy].z, wr[dy][2].z, acc.z);
            acc.w = fmaf(colC[dy].w, wr[dy][2].w, acc.w);
        }
        float o0 = gelu_exact(acc.x), o1 = gelu_exact(acc.y);
        float o2 = gelu_exact(acc.z), o3 = gelu_exact(acc.w);
        __nv_bfloat16 h0 = __float2bfloat16(o0), h1 = __float2bfloat16(o1);
        __nv_bfloat16 h2 = __float2bfloat16(o2), h3 = __float2bfloat16(o3);
        size_t idx = ((size_t)r * 64 + x) * CDIM + c0;
        __nv_bfloat162* hp = reinterpret_cast<__nv_bfloat162*>(ohi + idx);
        hp[0] = __nv_bfloat162(h0, h1);
        hp[1] = __nv_bfloat162(h2, h3);
        __nv_bfloat162* lp = reinterpret_cast<__nv_bfloat162*>(olo + idx);
        lp[0] = __nv_bfloat162(__float2bfloat16(o0 - __bfloat162float(h0)),
                               __float2bfloat16(o1 - __bfloat162float(h1)));
        lp[1] = __nv_bfloat162(__float2bfloat16(o2 - __bfloat162float(h2)),
                               __float2bfloat16(o3 - __bfloat162float(h3)));
        // slide window
#pragma unroll
        for (int dy = 0; dy < 3; dy++) { colA[dy] = colB[dy]; colB[dy] = colC[dy]; }
    }
}

// ---------------------------------------------------------------------------
// fc3 for cls branch (N=1): warp-per-token dot, K=256, reads hi/lo activation.
// ---------------------------------------------------------------------------
__global__ __launch_bounds__(256) void fc_dot_kernel(
    const __nv_bfloat16* __restrict__ Ahi, const __nv_bfloat16* __restrict__ Alo,
    const float* __restrict__ w, const float* __restrict__ b,
    float* __restrict__ out)
{
    __shared__ float ws[CDIM];
    int tid = threadIdx.x;
    ws[tid] = w[tid];
    __syncthreads();
    int warp = tid >> 5, lane = tid & 31;
    int token = blockIdx.x * 8 + warp;
    const __nv_bfloat16* ah = Ahi + (size_t)token * CDIM;
    const __nv_bfloat16* al = Alo + (size_t)token * CDIM;
    float acc = 0.f;
#pragma unroll
    for (int i = 0; i < 8; i++) {
        int k = lane + 32 * i;
        float a = __bfloat162float(ah[k]) + __bfloat162float(al[k]);
        acc = fmaf(a, ws[k], acc);
    }
#pragma unroll
    for (int o = 16; o; o >>= 1) acc += __shfl_xor_sync(0xffffffffu, acc, o);
    if (lane == 0) out[token] = acc + b[0];
}

// ---------------------------------------------------------------------------
// Fused tail: softmax(17) -> boxes, top-4+mean -> rc1(relu) -> rc2(sigmoid),
// cls = sigmoid(cls_logit) * q
// ---------------------------------------------------------------------------
__global__ __launch_bounds__(256) void fuse_tail_kernel(
    const float* __restrict__ reg, const float* __restrict__ clsl,
    const float* __restrict__ rc1w, const float* __restrict__ rc1b,
    const float* __restrict__ rc2w, const float* __restrict__ rc2b,
    float* __restrict__ cls_out, float* __restrict__ boxes_out)
{
    __shared__ float s_w1[64 * 20];
    __shared__ float s_b1[64];
    __shared__ float s_w2[64];
    int tid = threadIdx.x;
    for (int i = tid; i < 64 * 20; i += 256) s_w1[i] = rc1w[i];
    if (tid < 64) { s_b1[tid] = rc1b[tid]; s_w2[tid] = rc2w[tid]; }
    __syncthreads();

    int token = blockIdx.x * 256 + tid;
    const float* r = reg + (size_t)token * REGC;

    float stat[20];
#pragma unroll
    for (int side = 0; side < NSIDE; side++) {
        float v[NBIN];
#pragma unroll
        for (int i = 0; i < NBIN; i++) v[i] = r[side * NBIN + i];
        float m = v[0];
#pragma unroll
        for (int i = 1; i < NBIN; i++) m = fmaxf(m, v[i]);
        float p[NBIN];
        float s = 0.f, d = 0.f;
#pragma unroll
        for (int i = 0; i < NBIN; i++) {
            float e = expf(v[i] - m);
            p[i] = e;
            s += e;
            d += e * (float)i;
        }
        boxes_out[(size_t)token * 4 + side] = d / (s * 16.f);
        float inv = 1.f / s;
#pragma unroll
        for (int i = 0; i < NBIN; i++) p[i] *= inv;

        unsigned used = 0;
        float mean = 0.f;
#pragma unroll
        for (int k = 0; k < 4; k++) {
            float best = -1.f;
            int bi = 0;
#pragma unroll
            for (int i = 0; i < NBIN; i++) {
                bool ok = (((used >> i) & 1u) == 0u) && (p[i] > best);
                best = ok ? p[i] : best;
                bi = ok ? i : bi;
            }
            used |= (1u << bi);
            stat[side * 5 + k] = best;
            mean += best;
        }
        stat[side * 5 + 4] = mean * 0.25f;
    }

    float qsum = 0.f;
#pragma unroll 4
    for (int o = 0; o < 64; o++) {
        float a = s_b1[o];
#pragma unroll
        for (int c = 0; c < 20; c++) a = fmaf(s_w1[o * 20 + c], stat[c], a);
        a = fmaxf(a, 0.f);
        qsum = fmaf(s_w2[o], a, qsum);
    }
    float q = 1.f / (1.f + expf(-(qsum + rc2b[0])));
    float cl = 1.f / (1.f + expf(-clsl[token]));
    cls_out[token] = cl * q;
}

// ---------------------------------------------------------------------------
// Launch
// ---------------------------------------------------------------------------
extern "C" void kernel_launch(void* const* d_in, const int* in_sizes, int n_in,
                              void* d_out, int out_size)
{
    (void)in_sizes; (void)n_in; (void)out_size;
    const float* x      = (const float*)d_in[0];
    const float* c_fc1w = (const float*)d_in[1];
    const float* c_fc1b = (const float*)d_in[2];
    const float* c_dw1w = (const float*)d_in[3];
    const float* c_dw1b = (const float*)d_in[4];
    const float* c_fc2w = (const float*)d_in[5];
    const float* c_fc2b = (const float*)d_in[6];
    const float* c_dw2w = (const float*)d_in[7];
    const float* c_dw2b = (const float*)d_in[8];
    const float* c_fc3w = (const float*)d_in[9];
    const float* c_fc3b = (const float*)d_in[10];
    const float* r_fc1w = (const float*)d_in[11];
    const float* r_fc1b = (const float*)d_in[12];
    const float* r_dw1w = (const float*)d_in[13];
    const float* r_dw1b = (const float*)d_in[14];
    const float* r_fc2w = (const float*)d_in[15];
    const float* r_fc2b = (const float*)d_in[16];
    const float* r_dw2w = (const float*)d_in[17];
    const float* r_dw2b = (const float*)d_in[18];
    const float* r_fc3w = (const float*)d_in[19];
    const float* r_fc3b = (const float*)d_in[20];
    const float* rc1w   = (const float*)d_in[21];
    const float* rc1b   = (const float*)d_in[22];
    const float* rc2w   = (const float*)d_in[23];
    const float* rc2b   = (const float*)d_in[24];

    float* out = (float*)d_out;
    float* out_cls = out + OUT_CLS_OFF;
    float* out_box = out + OUT_BOX_OFF;
    float* out_reg = out + OUT_REG_OFF;

    float *bufA = nullptr, *clsl = nullptr;
    __nv_bfloat16 *xhi, *xlo, *ahi, *alo, *whi, *wlo;
    cudaGetSymbolAddress((void**)&bufA, g_bufA);
    cudaGetSymbolAddress((void**)&clsl, g_cls_logit);
    cudaGetSymbolAddress((void**)&xhi, g_xhi);
    cudaGetSymbolAddress((void**)&xlo, g_xlo);
    cudaGetSymbolAddress((void**)&ahi, g_ahi);
    cudaGetSymbolAddress((void**)&alo, g_alo);
    cudaGetSymbolAddress((void**)&whi, g_whi);
    cudaGetSymbolAddress((void**)&wlo, g_wlo);

    cudaFuncSetAttribute(gemm_bf16x3_kernel,
                         cudaFuncAttributeMaxDynamicSharedMemorySize, GEMM_SMEM);

    // Upfront conversions
    convert_x_kernel<<<(MTOK * CDIM) / 1024, 256>>>(x, xhi, xlo);
    convert_w5_kernel<<<(WTOTAL + 255) / 256, 256>>>(
        c_fc1w, c_fc2w, r_fc1w, r_fc2w, r_fc3w, whi, wlo);

    auto gemm = [&](const __nv_bfloat16* Ah, const __nv_bfloat16* Al,
                    int woff, const float* B, float* Cout, int N) {
        dim3 grid(MTOK / BM, (N + BN - 1) / BN);
        gemm_bf16x3_kernel<<<grid, 256, GEMM_SMEM>>>(
            Ah, Al, whi + woff, wlo + woff, B, Cout, N);
    };

    // ---- cls branch ----
    gemm(xhi, xlo, WOFF_CFC1, c_fc1b, bufA, CDIM);
    dwconv_gelu_split_kernel<<<2048, 256>>>(bufA, c_dw1w, c_dw1b, ahi, alo);
    gemm(ahi, alo, WOFF_CFC2, c_fc2b, bufA, CDIM);
    dwconv_gelu_split_kernel<<<2048, 256>>>(bufA, c_dw2w, c_dw2b, ahi, alo);
    fc_dot_kernel<<<MTOK / 8, 256>>>(ahi, alo, c_fc3w, c_fc3b, clsl);

    // ---- reg branch ----
    gemm(xhi, xlo, WOFF_RFC1, r_fc1b, bufA, CDIM);
    dwconv_gelu_split_kernel<<<2048, 256>>>(bufA, r_dw1w, r_dw1b, ahi, alo);
    gemm(ahi, alo, WOFF_RFC2, r_fc2b, bufA, CDIM);
    dwconv_gelu_split_kernel<<<2048, 256>>>(bufA, r_dw2w, r_dw2b, ahi, alo);
    gemm(ahi, alo, WOFF_RFC3, r_fc3b, out_reg, REGC);

    // ---- fused tail ----
    fuse_tail_kernel<<<MTOK / 256, 256>>>(out_reg, clsl, rc1w, rc1b, rc2w, rc2b,
                                          out_cls, out_box);
}